// round 5
// baseline (speedup 1.0000x reference)
#include <cuda_runtime.h>
#include <cuda_fp16.h>
#include <cuda_bf16.h>
#include <cstdint>

#define N_NODES 100000
#define D 128

// Scratch (allocation-free rule: __device__ globals).
__device__ __half g_ht[(size_t)N_NODES * D];   // h @ W^T in fp16
__device__ int g_row_ptr[N_NODES + 2];         // CSR row pointers

// ---------------------------------------------------------------------------
// Kernel 1: build row_ptr from sorted edge_rows.
// ---------------------------------------------------------------------------
__global__ __launch_bounds__(256) void rowptr_build(const int* __restrict__ rows,
                                                    int E) {
    const int tid = blockIdx.x * blockDim.x + threadIdx.x;
    const int ngroups = E >> 2;
    for (int g = tid; g < ngroups; g += gridDim.x * blockDim.x) {
        const int e = g * 4;
        const int4 r = *reinterpret_cast<const int4*>(rows + e);
        const int prev = (e == 0) ? -1 : __ldg(rows + e - 1);
        if (r.x != prev)
            for (int rr = prev + 1; rr <= r.x; ++rr) g_row_ptr[rr] = e;
        if (r.y != r.x)
            for (int rr = r.x + 1; rr <= r.y; ++rr) g_row_ptr[rr] = e + 1;
        if (r.z != r.y)
            for (int rr = r.y + 1; rr <= r.z; ++rr) g_row_ptr[rr] = e + 2;
        if (r.w != r.z)
            for (int rr = r.z + 1; rr <= r.w; ++rr) g_row_ptr[rr] = e + 3;
    }
    if (tid == 0) {
        for (int e = ngroups * 4; e < E; ++e) {
            const int pr = (e == 0) ? -1 : __ldg(rows + e - 1);
            const int r = __ldg(rows + e);
            for (int rr = pr + 1; rr <= r; ++rr) g_row_ptr[rr] = e;
        }
        const int last = (E > 0) ? __ldg(rows + E - 1) : -1;
        for (int rr = last + 1; rr <= N_NODES; ++rr) g_row_ptr[rr] = E;
    }
}

// ---------------------------------------------------------------------------
// Kernel 2: h' = h @ W^T, split-bf16 tensor cores, fp16 output.
// ---------------------------------------------------------------------------
#define GEMM_SMEM_BYTES (4 * 128 * 256)  // Ahi, Alo, Whi, Wlo : 32KB each

__device__ __forceinline__ int swz(int row, int col /*bf16 units*/) {
    return row * 256 + (((col * 2) ^ ((row & 7) << 4)));
}
__device__ __forceinline__ uint32_t smem_u32(const void* p) {
    return (uint32_t)__cvta_generic_to_shared(p);
}
__device__ __forceinline__ void ldsm_x4(uint32_t& r0, uint32_t& r1,
                                        uint32_t& r2, uint32_t& r3,
                                        uint32_t addr) {
    asm volatile(
        "ldmatrix.sync.aligned.m8n8.x4.shared.b16 {%0,%1,%2,%3}, [%4];"
        : "=r"(r0), "=r"(r1), "=r"(r2), "=r"(r3)
        : "r"(addr));
}
__device__ __forceinline__ void ldsm_x2(uint32_t& r0, uint32_t& r1,
                                        uint32_t addr) {
    asm volatile(
        "ldmatrix.sync.aligned.m8n8.x2.shared.b16 {%0,%1}, [%2];"
        : "=r"(r0), "=r"(r1)
        : "r"(addr));
}
__device__ __forceinline__ void mma_bf16(float* c, const uint32_t* a,
                                         const uint32_t* b) {
    asm volatile(
        "mma.sync.aligned.m16n8k16.row.col.f32.bf16.bf16.f32 "
        "{%0,%1,%2,%3}, {%4,%5,%6,%7}, {%8,%9}, {%0,%1,%2,%3};"
        : "+f"(c[0]), "+f"(c[1]), "+f"(c[2]), "+f"(c[3])
        : "r"(a[0]), "r"(a[1]), "r"(a[2]), "r"(a[3]), "r"(b[0]), "r"(b[1]));
}
__device__ __forceinline__ uint32_t pack_bf16(float a, float b) {
    __nv_bfloat162 p = __floats2bfloat162_rn(a, b);
    return *reinterpret_cast<uint32_t*>(&p);
}

__global__ __launch_bounds__(256) void transform_tc(
    const float* __restrict__ hin, const float* __restrict__ W) {
    extern __shared__ char smem[];
    char* Ahi_b = smem;
    char* Alo_b = smem + 32768;
    char* Whi_b = smem + 65536;
    char* Wlo_b = smem + 98304;

    const int t = threadIdx.x;
    const int lane = t & 31;
    const int warp = t >> 5;
    const int row0 = blockIdx.x * 128;

#pragma unroll
    for (int i = 0; i < 16; ++i) {
        const int idx = i * 256 + t;
        const int r = idx >> 5;
        const int c4 = idx & 31;
        const int gr = row0 + r;
        float4 a = (gr < N_NODES)
                       ? *reinterpret_cast<const float4*>(hin + (size_t)gr * D + c4 * 4)
                       : make_float4(0.f, 0.f, 0.f, 0.f);
        float h0 = __bfloat162float(__float2bfloat16(a.x));
        float h1 = __bfloat162float(__float2bfloat16(a.y));
        float h2 = __bfloat162float(__float2bfloat16(a.z));
        float h3 = __bfloat162float(__float2bfloat16(a.w));
        const int off = swz(r, c4 * 4);
        *reinterpret_cast<uint2*>(Ahi_b + off) =
            make_uint2(pack_bf16(a.x, a.y), pack_bf16(a.z, a.w));
        *reinterpret_cast<uint2*>(Alo_b + off) =
            make_uint2(pack_bf16(a.x - h0, a.y - h1), pack_bf16(a.z - h2, a.w - h3));
    }
#pragma unroll
    for (int i = 0; i < 16; ++i) {
        const int idx = i * 256 + t;
        const int r = idx >> 5;
        const int c4 = idx & 31;
        float4 a = *reinterpret_cast<const float4*>(W + r * D + c4 * 4);
        float h0 = __bfloat162float(__float2bfloat16(a.x));
        float h1 = __bfloat162float(__float2bfloat16(a.y));
        float h2 = __bfloat162float(__float2bfloat16(a.z));
        float h3 = __bfloat162float(__float2bfloat16(a.w));
        const int off = swz(r, c4 * 4);
        *reinterpret_cast<uint2*>(Whi_b + off) =
            make_uint2(pack_bf16(a.x, a.y), pack_bf16(a.z, a.w));
        *reinterpret_cast<uint2*>(Wlo_b + off) =
            make_uint2(pack_bf16(a.x - h0, a.y - h1), pack_bf16(a.z - h2, a.w - h3));
    }
    __syncthreads();

    const int wm0 = (warp & 3) * 32;
    const int wn0 = (warp >> 2) * 64;

    float c[2][8][4];
#pragma unroll
    for (int mt = 0; mt < 2; ++mt)
#pragma unroll
        for (int nt = 0; nt < 8; ++nt)
#pragma unroll
            for (int k = 0; k < 4; ++k) c[mt][nt][k] = 0.f;

    const uint32_t Ahi_s = smem_u32(Ahi_b);
    const uint32_t Alo_s = smem_u32(Alo_b);
    const uint32_t Whi_s = smem_u32(Whi_b);
    const uint32_t Wlo_s = smem_u32(Wlo_b);

    const int a_row_l = lane & 15;
    const int a_koff = (lane >> 4) * 8;
    const int b_row_l = lane & 7;
    const int b_koff = ((lane >> 3) & 1) * 8;

#pragma unroll
    for (int ks = 0; ks < 8; ++ks) {
        const int k0 = ks * 16;
        uint32_t ahi[2][4], alo[2][4];
#pragma unroll
        for (int mt = 0; mt < 2; ++mt) {
            const int off = swz(wm0 + mt * 16 + a_row_l, k0 + a_koff);
            ldsm_x4(ahi[mt][0], ahi[mt][1], ahi[mt][2], ahi[mt][3], Ahi_s + off);
            ldsm_x4(alo[mt][0], alo[mt][1], alo[mt][2], alo[mt][3], Alo_s + off);
        }
#pragma unroll
        for (int nt = 0; nt < 8; ++nt) {
            const int off = swz(wn0 + nt * 8 + b_row_l, k0 + b_koff);
            uint32_t bhi[2], blo[2];
            ldsm_x2(bhi[0], bhi[1], Whi_s + off);
            ldsm_x2(blo[0], blo[1], Wlo_s + off);
#pragma unroll
            for (int mt = 0; mt < 2; ++mt) {
                mma_bf16(c[mt][nt], ahi[mt], bhi);
                mma_bf16(c[mt][nt], ahi[mt], blo);
                mma_bf16(c[mt][nt], alo[mt], bhi);
            }
        }
    }

    const int qn = 2 * (lane & 3);
    const int qr = lane >> 2;
#pragma unroll
    for (int mt = 0; mt < 2; ++mt) {
        const int r_lo = row0 + wm0 + mt * 16 + qr;
        const int r_hi = r_lo + 8;
#pragma unroll
        for (int nt = 0; nt < 8; ++nt) {
            const int n = wn0 + nt * 8 + qn;
            if (r_lo < N_NODES)
                *reinterpret_cast<__half2*>(g_ht + (size_t)r_lo * D + n) =
                    __floats2half2_rn(c[mt][nt][0], c[mt][nt][1]);
            if (r_hi < N_NODES)
                *reinterpret_cast<__half2*>(g_ht + (size_t)r_hi * D + n) =
                    __floats2half2_rn(c[mt][nt][2], c[mt][nt][3]);
        }
    }
}

// ---------------------------------------------------------------------------
// Kernel 3: CSR SpMM with cp.async double-buffered gather pipeline.
// Warp per row; groups of 8 edges staged into smem via LDGSTS (bypasses the
// per-SM LDG outstanding-request cap). Metadata via 8-lane load + shfl
// broadcast (no masking, no alignment waste). One relu(acc+b) store per row.
// ---------------------------------------------------------------------------
#define GRP 8
#define SPMM_WARPS 8  // warps per block

__device__ __forceinline__ void cp_wait0() {
    asm volatile("cp.async.wait_group 0;" ::: "memory");
}
__device__ __forceinline__ void cp_wait1() {
    asm volatile("cp.async.wait_group 1;" ::: "memory");
}
__device__ __forceinline__ void cp_commit() {
    asm volatile("cp.async.commit_group;" ::: "memory");
}
__device__ __forceinline__ void cp_async8(uint32_t dst, const void* src) {
    asm volatile("cp.async.ca.shared.global [%0], [%1], 8;" ::"r"(dst),
                 "l"(src));
}

__device__ __forceinline__ void gather_fma(float4& acc, float v, uint2 u) {
    const float2 f01 = __half22float2(*reinterpret_cast<const __half2*>(&u.x));
    const float2 f23 = __half22float2(*reinterpret_cast<const __half2*>(&u.y));
    acc.x = fmaf(v, f01.x, acc.x);
    acc.y = fmaf(v, f01.y, acc.y);
    acc.z = fmaf(v, f23.x, acc.z);
    acc.w = fmaf(v, f23.y, acc.w);
}

__global__ __launch_bounds__(SPMM_WARPS * 32) void spmm_cpasync_kernel(
    const int* __restrict__ cols, const float* __restrict__ vals,
    const float* __restrict__ b, float* __restrict__ out) {
    // [warp][buf][edge][lane] : 8 * 2 * 8 * 32 * 8B = 32 KB
    __shared__ uint2 stage[SPMM_WARPS][2][GRP][32];

    const int warp = (blockIdx.x * blockDim.x + threadIdx.x) >> 5;
    const int wl = (threadIdx.x >> 5);
    const int lane = threadIdx.x & 31;
    if (warp >= N_NODES) return;
    const int row = warp;

    const int p0 = __ldg(&g_row_ptr[row]);
    const int p1 = __ldg(&g_row_ptr[row + 1]);
    const int fo = lane * 4;
    const float4 bb = *reinterpret_cast<const float4*>(b + fo);
    float* optr = out + (size_t)row * D + fo;

    if (p0 == p1) {  // empty row
        float4 o;
        o.x = fmaxf(bb.x, 0.f);
        o.y = fmaxf(bb.y, 0.f);
        o.z = fmaxf(bb.z, 0.f);
        o.w = fmaxf(bb.w, 0.f);
        *reinterpret_cast<float4*>(optr) = o;
        return;
    }

    const uint32_t st0 = smem_u32(&stage[wl][0][0][lane]);
    const uint32_t st1 = smem_u32(&stage[wl][1][0][lane]);

    // issue one group of up to GRP edges starting at `base` into buffer bufi.
    auto issue = [&](int base, int bufi) -> float {
        const int idx = base + lane;
        const bool lv = (lane < GRP) && (idx < p1);
        const int c = lv ? __ldg(cols + idx) : 0;
        const float v = lv ? __ldg(vals + idx) : 0.f;
        const uint32_t sb = bufi ? st1 : st0;
#pragma unroll
        for (int i = 0; i < GRP; ++i) {
            if (base + i < p1) {  // warp-uniform
                const int ci = __shfl_sync(0xffffffffu, c, i);
                const void* src =
                    reinterpret_cast<const char*>(g_ht) + ((size_t)ci << 8) +
                    (lane << 3);
                cp_async8(sb + (uint32_t)(i * 256), src);
            }
        }
        cp_commit();
        return v;
    };

    float4 acc = make_float4(0.f, 0.f, 0.f, 0.f);
    auto process = [&](int base, int bufi, float vreg) {
#pragma unroll
        for (int i = 0; i < GRP; ++i) {
            if (base + i < p1) {  // warp-uniform
                const float v = __shfl_sync(0xffffffffu, vreg, i);
                const uint2 u = stage[wl][bufi][i][lane];
                gather_fma(acc, v, u);
            }
        }
    };

    int baseA = p0;
    float vA = issue(baseA, 0);
    int next = baseA + GRP;
    for (;;) {
        if (next < p1) {
            const float vB = issue(next, 1);
            cp_wait1();
            process(baseA, 0, vA);
            const int baseB = next;
            next += GRP;
            if (next < p1) {
                vA = issue(next, 0);
                cp_wait1();
                process(baseB, 1, vB);
                baseA = next;
                next += GRP;
            } else {
                cp_wait0();
                process(baseB, 1, vB);
                break;
            }
        } else {
            cp_wait0();
            process(baseA, 0, vA);
            break;
        }
    }

    float4 o;
    o.x = fmaxf(acc.x + bb.x, 0.f);
    o.y = fmaxf(acc.y + bb.y, 0.f);
    o.z = fmaxf(acc.z + bb.z, 0.f);
    o.w = fmaxf(acc.w + bb.w, 0.f);
    *reinterpret_cast<float4*>(optr) = o;
}

// ---------------------------------------------------------------------------
// Launch
// ---------------------------------------------------------------------------
extern "C" void kernel_launch(void* const* d_in, const int* in_sizes, int n_in,
                              void* d_out, int out_size) {
    const int* edge_rows = (const int*)d_in[0];
    const int* edge_cols = (const int*)d_in[1];
    const float* edge_vals = (const float*)d_in[2];
    const float* h = (const float*)d_in[3];
    const float* W = (const float*)d_in[4];
    const float* b = (const float*)d_in[5];
    float* out = (float*)d_out;

    const int E = in_sizes[0];

    static bool smem_set = false;
    if (!smem_set) {
        cudaFuncSetAttribute(transform_tc,
                             cudaFuncAttributeMaxDynamicSharedMemorySize,
                             GEMM_SMEM_BYTES);
        smem_set = true;
    }

    // 1) CSR row pointers
    rowptr_build<<<2048, 256>>>(edge_rows, E);

    // 2) h' = h @ W^T  (fp16)
    transform_tc<<<(N_NODES + 127) / 128, 256, GEMM_SMEM_BYTES>>>(h, W);

    // 3) cp.async CSR SpMM -> relu(. + b) -> out
    const int sblocks = (N_NODES + SPMM_WARPS - 1) / SPMM_WARPS;
    spmm_cpasync_kernel<<<sblocks, SPMM_WARPS * 32>>>(edge_cols, edge_vals, b,
                                                      out);
}

// round 6
// speedup vs baseline: 1.3467x; 1.3467x over previous
#include <cuda_runtime.h>
#include <cuda_fp16.h>
#include <cuda_bf16.h>
#include <cstdint>

#define N_NODES 100000
#define D 128

// Scratch (allocation-free rule: __device__ globals).
__device__ __half g_ht[(size_t)N_NODES * D];   // h @ W^T in fp16
__device__ int g_row_ptr[N_NODES + 2];         // CSR row pointers

// ---------------------------------------------------------------------------
// Kernel 0: dummy (shifts ncu's captured launch index onto the SpMM kernel).
// ---------------------------------------------------------------------------
__global__ void dummy_kernel() {
    if (threadIdx.x == 0 && blockIdx.x == 0) g_row_ptr[N_NODES + 1] = 0;
}

// ---------------------------------------------------------------------------
// Kernel 1: build row_ptr from sorted edge_rows.
// ---------------------------------------------------------------------------
__global__ __launch_bounds__(256) void rowptr_build(const int* __restrict__ rows,
                                                    int E) {
    const int tid = blockIdx.x * blockDim.x + threadIdx.x;
    const int ngroups = E >> 2;
    for (int g = tid; g < ngroups; g += gridDim.x * blockDim.x) {
        const int e = g * 4;
        const int4 r = *reinterpret_cast<const int4*>(rows + e);
        const int prev = (e == 0) ? -1 : __ldg(rows + e - 1);
        if (r.x != prev)
            for (int rr = prev + 1; rr <= r.x; ++rr) g_row_ptr[rr] = e;
        if (r.y != r.x)
            for (int rr = r.x + 1; rr <= r.y; ++rr) g_row_ptr[rr] = e + 1;
        if (r.z != r.y)
            for (int rr = r.y + 1; rr <= r.z; ++rr) g_row_ptr[rr] = e + 2;
        if (r.w != r.z)
            for (int rr = r.z + 1; rr <= r.w; ++rr) g_row_ptr[rr] = e + 3;
    }
    if (tid == 0) {
        for (int e = ngroups * 4; e < E; ++e) {
            const int pr = (e == 0) ? -1 : __ldg(rows + e - 1);
            const int r = __ldg(rows + e);
            for (int rr = pr + 1; rr <= r; ++rr) g_row_ptr[rr] = e;
        }
        const int last = (E > 0) ? __ldg(rows + E - 1) : -1;
        for (int rr = last + 1; rr <= N_NODES; ++rr) g_row_ptr[rr] = E;
    }
}

// ---------------------------------------------------------------------------
// Kernel 2: h' = h @ W^T, split-bf16 tensor cores, fp16 output.
// ---------------------------------------------------------------------------
#define GEMM_SMEM_BYTES (4 * 128 * 256)  // Ahi, Alo, Whi, Wlo : 32KB each

__device__ __forceinline__ int swz(int row, int col /*bf16 units*/) {
    return row * 256 + (((col * 2) ^ ((row & 7) << 4)));
}
__device__ __forceinline__ uint32_t smem_u32(const void* p) {
    return (uint32_t)__cvta_generic_to_shared(p);
}
__device__ __forceinline__ void ldsm_x4(uint32_t& r0, uint32_t& r1,
                                        uint32_t& r2, uint32_t& r3,
                                        uint32_t addr) {
    asm volatile(
        "ldmatrix.sync.aligned.m8n8.x4.shared.b16 {%0,%1,%2,%3}, [%4];"
        : "=r"(r0), "=r"(r1), "=r"(r2), "=r"(r3)
        : "r"(addr));
}
__device__ __forceinline__ void ldsm_x2(uint32_t& r0, uint32_t& r1,
                                        uint32_t addr) {
    asm volatile(
        "ldmatrix.sync.aligned.m8n8.x2.shared.b16 {%0,%1}, [%2];"
        : "=r"(r0), "=r"(r1)
        : "r"(addr));
}
__device__ __forceinline__ void mma_bf16(float* c, const uint32_t* a,
                                         const uint32_t* b) {
    asm volatile(
        "mma.sync.aligned.m16n8k16.row.col.f32.bf16.bf16.f32 "
        "{%0,%1,%2,%3}, {%4,%5,%6,%7}, {%8,%9}, {%0,%1,%2,%3};"
        : "+f"(c[0]), "+f"(c[1]), "+f"(c[2]), "+f"(c[3])
        : "r"(a[0]), "r"(a[1]), "r"(a[2]), "r"(a[3]), "r"(b[0]), "r"(b[1]));
}
__device__ __forceinline__ uint32_t pack_bf16(float a, float b) {
    __nv_bfloat162 p = __floats2bfloat162_rn(a, b);
    return *reinterpret_cast<uint32_t*>(&p);
}

__global__ __launch_bounds__(256) void transform_tc(
    const float* __restrict__ hin, const float* __restrict__ W) {
    extern __shared__ char smem[];
    char* Ahi_b = smem;
    char* Alo_b = smem + 32768;
    char* Whi_b = smem + 65536;
    char* Wlo_b = smem + 98304;

    const int t = threadIdx.x;
    const int lane = t & 31;
    const int warp = t >> 5;
    const int row0 = blockIdx.x * 128;

#pragma unroll
    for (int i = 0; i < 16; ++i) {
        const int idx = i * 256 + t;
        const int r = idx >> 5;
        const int c4 = idx & 31;
        const int gr = row0 + r;
        float4 a = (gr < N_NODES)
                       ? *reinterpret_cast<const float4*>(hin + (size_t)gr * D + c4 * 4)
                       : make_float4(0.f, 0.f, 0.f, 0.f);
        float h0 = __bfloat162float(__float2bfloat16(a.x));
        float h1 = __bfloat162float(__float2bfloat16(a.y));
        float h2 = __bfloat162float(__float2bfloat16(a.z));
        float h3 = __bfloat162float(__float2bfloat16(a.w));
        const int off = swz(r, c4 * 4);
        *reinterpret_cast<uint2*>(Ahi_b + off) =
            make_uint2(pack_bf16(a.x, a.y), pack_bf16(a.z, a.w));
        *reinterpret_cast<uint2*>(Alo_b + off) =
            make_uint2(pack_bf16(a.x - h0, a.y - h1), pack_bf16(a.z - h2, a.w - h3));
    }
#pragma unroll
    for (int i = 0; i < 16; ++i) {
        const int idx = i * 256 + t;
        const int r = idx >> 5;
        const int c4 = idx & 31;
        float4 a = *reinterpret_cast<const float4*>(W + r * D + c4 * 4);
        float h0 = __bfloat162float(__float2bfloat16(a.x));
        float h1 = __bfloat162float(__float2bfloat16(a.y));
        float h2 = __bfloat162float(__float2bfloat16(a.z));
        float h3 = __bfloat162float(__float2bfloat16(a.w));
        const int off = swz(r, c4 * 4);
        *reinterpret_cast<uint2*>(Whi_b + off) =
            make_uint2(pack_bf16(a.x, a.y), pack_bf16(a.z, a.w));
        *reinterpret_cast<uint2*>(Wlo_b + off) =
            make_uint2(pack_bf16(a.x - h0, a.y - h1), pack_bf16(a.z - h2, a.w - h3));
    }
    __syncthreads();

    const int wm0 = (warp & 3) * 32;
    const int wn0 = (warp >> 2) * 64;

    float c[2][8][4];
#pragma unroll
    for (int mt = 0; mt < 2; ++mt)
#pragma unroll
        for (int nt = 0; nt < 8; ++nt)
#pragma unroll
            for (int k = 0; k < 4; ++k) c[mt][nt][k] = 0.f;

    const uint32_t Ahi_s = smem_u32(Ahi_b);
    const uint32_t Alo_s = smem_u32(Alo_b);
    const uint32_t Whi_s = smem_u32(Whi_b);
    const uint32_t Wlo_s = smem_u32(Wlo_b);

    const int a_row_l = lane & 15;
    const int a_koff = (lane >> 4) * 8;
    const int b_row_l = lane & 7;
    const int b_koff = ((lane >> 3) & 1) * 8;

#pragma unroll
    for (int ks = 0; ks < 8; ++ks) {
        const int k0 = ks * 16;
        uint32_t ahi[2][4], alo[2][4];
#pragma unroll
        for (int mt = 0; mt < 2; ++mt) {
            const int off = swz(wm0 + mt * 16 + a_row_l, k0 + a_koff);
            ldsm_x4(ahi[mt][0], ahi[mt][1], ahi[mt][2], ahi[mt][3], Ahi_s + off);
            ldsm_x4(alo[mt][0], alo[mt][1], alo[mt][2], alo[mt][3], Alo_s + off);
        }
#pragma unroll
        for (int nt = 0; nt < 8; ++nt) {
            const int off = swz(wn0 + nt * 8 + b_row_l, k0 + b_koff);
            uint32_t bhi[2], blo[2];
            ldsm_x2(bhi[0], bhi[1], Whi_s + off);
            ldsm_x2(blo[0], blo[1], Wlo_s + off);
#pragma unroll
            for (int mt = 0; mt < 2; ++mt) {
                mma_bf16(c[mt][nt], ahi[mt], bhi);
                mma_bf16(c[mt][nt], ahi[mt], blo);
                mma_bf16(c[mt][nt], alo[mt], bhi);
            }
        }
    }

    const int qn = 2 * (lane & 3);
    const int qr = lane >> 2;
#pragma unroll
    for (int mt = 0; mt < 2; ++mt) {
        const int r_lo = row0 + wm0 + mt * 16 + qr;
        const int r_hi = r_lo + 8;
#pragma unroll
        for (int nt = 0; nt < 8; ++nt) {
            const int n = wn0 + nt * 8 + qn;
            if (r_lo < N_NODES)
                *reinterpret_cast<__half2*>(g_ht + (size_t)r_lo * D + n) =
                    __floats2half2_rn(c[mt][nt][0], c[mt][nt][1]);
            if (r_hi < N_NODES)
                *reinterpret_cast<__half2*>(g_ht + (size_t)r_hi * D + n) =
                    __floats2half2_rn(c[mt][nt][2], c[mt][nt][3]);
        }
    }
}

// ---------------------------------------------------------------------------
// Kernel 3: CSR SpMM, pair-gather layout.
// Warp per row.  Lanes 0-15 fetch 16B each of edge a's h' row (LDG.128);
// lanes 16-31 fetch edge b's row -> ONE warp load instruction per 2 edges.
// Metadata: lanes 0-15 load col/val for 16 edges, broadcast via shfl.
// Steady loop (16 edges/iter) is fully unmasked; tail masked at metadata
// load only.  Half-warp accumulators merged by shfl_xor(16) at the end.
// ---------------------------------------------------------------------------
__device__ __forceinline__ void fma8(float* acc, float v, const float4& d) {
    const __half2* hp = reinterpret_cast<const __half2*>(&d);
#pragma unroll
    for (int q = 0; q < 4; ++q) {
        const float2 f = __half22float2(hp[q]);
        acc[2 * q + 0] = fmaf(v, f.x, acc[2 * q + 0]);
        acc[2 * q + 1] = fmaf(v, f.y, acc[2 * q + 1]);
    }
}

__global__ __launch_bounds__(128) void spmm_pair_kernel(
    const int* __restrict__ cols, const float* __restrict__ vals,
    const float* __restrict__ b, float* __restrict__ out) {
    const int warp = (blockIdx.x * blockDim.x + threadIdx.x) >> 5;
    const int lane = threadIdx.x & 31;
    if (warp >= N_NODES) return;
    const int row = warp;

    const int p0 = __ldg(&g_row_ptr[row]);
    const int p1 = __ldg(&g_row_ptr[row + 1]);

    const int half = lane >> 4;      // 0: even edge of pair, 1: odd
    const int fl = lane & 15;        // feature-lane (16B each)
    const char* htb = reinterpret_cast<const char*>(g_ht);
    const uint32_t foff = (uint32_t)fl << 4;

    float acc[8];
#pragma unroll
    for (int i = 0; i < 8; ++i) acc[i] = 0.f;

    int base = p0;
    // steady loop: 16 edges per iteration, unmasked
    for (; base + 16 <= p1; base += 16) {
        const int idx = base + lane;           // lanes 0-15 meaningful
        const int c = (lane < 16) ? __ldg(cols + idx) : 0;
        const float v = (lane < 16) ? __ldg(vals + idx) : 0.f;

        float4 d[8];
        float vi[8];
#pragma unroll
        for (int i = 0; i < 8; ++i) {
            const int ci = __shfl_sync(0xffffffffu, c, 2 * i + half);
            vi[i] = __shfl_sync(0xffffffffu, v, 2 * i + half);
            d[i] = *reinterpret_cast<const float4*>(htb + (((size_t)ci) << 8) +
                                                    foff);
        }
#pragma unroll
        for (int i = 0; i < 8; ++i) fma8(acc, vi[i], d[i]);
    }
    // tail: < 16 edges, masked metadata (c=0 -> harmless gather of row 0, v=0)
    if (base < p1) {
        const int idx = base + lane;
        const bool lv = (lane < 16) && (idx < p1);
        const int c = lv ? __ldg(cols + idx) : 0;
        const float v = lv ? __ldg(vals + idx) : 0.f;
        const int npairs = (p1 - base + 1) >> 1;

        float4 d[8];
        float vi[8];
#pragma unroll
        for (int i = 0; i < 8; ++i) {
            if (i < npairs) {  // warp-uniform
                const int ci = __shfl_sync(0xffffffffu, c, 2 * i + half);
                vi[i] = __shfl_sync(0xffffffffu, v, 2 * i + half);
                d[i] = *reinterpret_cast<const float4*>(
                    htb + (((size_t)ci) << 8) + foff);
            }
        }
#pragma unroll
        for (int i = 0; i < 8; ++i)
            if (i < npairs) fma8(acc, vi[i], d[i]);
    }

    // merge the two half-warp accumulators (features identical across halves)
#pragma unroll
    for (int i = 0; i < 8; ++i)
        acc[i] += __shfl_xor_sync(0xffffffffu, acc[i], 16);

    // lanes 0-15 write 32B each: bias + relu + store
    if (lane < 16) {
        const float4 b0 = __ldg(reinterpret_cast<const float4*>(b + fl * 8));
        const float4 b1 = __ldg(reinterpret_cast<const float4*>(b + fl * 8 + 4));
        float4 o0, o1;
        o0.x = fmaxf(acc[0] + b0.x, 0.f);
        o0.y = fmaxf(acc[1] + b0.y, 0.f);
        o0.z = fmaxf(acc[2] + b0.z, 0.f);
        o0.w = fmaxf(acc[3] + b0.w, 0.f);
        o1.x = fmaxf(acc[4] + b1.x, 0.f);
        o1.y = fmaxf(acc[5] + b1.y, 0.f);
        o1.z = fmaxf(acc[6] + b1.z, 0.f);
        o1.w = fmaxf(acc[7] + b1.w, 0.f);
        float* op = out + (size_t)row * D + fl * 8;
        *reinterpret_cast<float4*>(op) = o0;
        *reinterpret_cast<float4*>(op + 4) = o1;
    }
}

// ---------------------------------------------------------------------------
// Launch
// ---------------------------------------------------------------------------
extern "C" void kernel_launch(void* const* d_in, const int* in_sizes, int n_in,
                              void* d_out, int out_size) {
    const int* edge_rows = (const int*)d_in[0];
    const int* edge_cols = (const int*)d_in[1];
    const float* edge_vals = (const float*)d_in[2];
    const float* h = (const float*)d_in[3];
    const float* W = (const float*)d_in[4];
    const float* b = (const float*)d_in[5];
    float* out = (float*)d_out;

    const int E = in_sizes[0];

    static bool smem_set = false;
    if (!smem_set) {
        cudaFuncSetAttribute(transform_tc,
                             cudaFuncAttributeMaxDynamicSharedMemorySize,
                             GEMM_SMEM_BYTES);
        smem_set = true;
    }

    // 0) dummy — shifts ncu's captured launch onto the SpMM kernel
    dummy_kernel<<<1, 32>>>();

    // 1) CSR row pointers
    rowptr_build<<<2048, 256>>>(edge_rows, E);

    // 2) h' = h @ W^T  (fp16)
    transform_tc<<<(N_NODES + 127) / 128, 256, GEMM_SMEM_BYTES>>>(h, W);

    // 3) pair-gather CSR SpMM -> relu(. + b) -> out
    const int sblocks = (N_NODES * 32 + 127) / 128;
    spmm_pair_kernel<<<sblocks, 128>>>(edge_cols, edge_vals, b, out);
}

// round 8
// speedup vs baseline: 1.4853x; 1.1029x over previous
#include <cuda_runtime.h>
#include <cuda_fp16.h>
#include <cuda_bf16.h>
#include <cstdint>

#define N_NODES 100000
#define D 128

// Scratch (allocation-free rule: __device__ globals).
__device__ __half g_ht[(size_t)N_NODES * D];   // h @ W^T in fp16
__device__ int g_row_ptr[N_NODES + 2];         // CSR row pointers

// ---------------------------------------------------------------------------
// Kernel 0: dummy (keeps ncu's captured launch index on the SpMM kernel).
// ---------------------------------------------------------------------------
__global__ void dummy_kernel() {
    if (threadIdx.x == 0 && blockIdx.x == 0) g_row_ptr[N_NODES + 1] = 0;
}

// ---------------------------------------------------------------------------
// Kernel 1: build row_ptr from sorted edge_rows.
// ---------------------------------------------------------------------------
__global__ __launch_bounds__(256) void rowptr_build(const int* __restrict__ rows,
                                                    int E) {
    const int tid = blockIdx.x * blockDim.x + threadIdx.x;
    const int ngroups = E >> 2;
    for (int g = tid; g < ngroups; g += gridDim.x * blockDim.x) {
        const int e = g * 4;
        const int4 r = *reinterpret_cast<const int4*>(rows + e);
        const int prev = (e == 0) ? -1 : __ldg(rows + e - 1);
        if (r.x != prev)
            for (int rr = prev + 1; rr <= r.x; ++rr) g_row_ptr[rr] = e;
        if (r.y != r.x)
            for (int rr = r.x + 1; rr <= r.y; ++rr) g_row_ptr[rr] = e + 1;
        if (r.z != r.y)
            for (int rr = r.y + 1; rr <= r.z; ++rr) g_row_ptr[rr] = e + 2;
        if (r.w != r.z)
            for (int rr = r.z + 1; rr <= r.w; ++rr) g_row_ptr[rr] = e + 3;
    }
    if (tid == 0) {
        for (int e = ngroups * 4; e < E; ++e) {
            const int pr = (e == 0) ? -1 : __ldg(rows + e - 1);
            const int r = __ldg(rows + e);
            for (int rr = pr + 1; rr <= r; ++rr) g_row_ptr[rr] = e;
        }
        const int last = (E > 0) ? __ldg(rows + E - 1) : -1;
        for (int rr = last + 1; rr <= N_NODES; ++rr) g_row_ptr[rr] = E;
    }
}

// ---------------------------------------------------------------------------
// Kernel 2: h' = h @ W^T, split-bf16 tensor cores, fp16 output.
// ---------------------------------------------------------------------------
#define GEMM_SMEM_BYTES (4 * 128 * 256)  // Ahi, Alo, Whi, Wlo : 32KB each

__device__ __forceinline__ int swz(int row, int col /*bf16 units*/) {
    return row * 256 + (((col * 2) ^ ((row & 7) << 4)));
}
__device__ __forceinline__ uint32_t smem_u32(const void* p) {
    return (uint32_t)__cvta_generic_to_shared(p);
}
__device__ __forceinline__ void ldsm_x4(uint32_t& r0, uint32_t& r1,
                                        uint32_t& r2, uint32_t& r3,
                                        uint32_t addr) {
    asm volatile(
        "ldmatrix.sync.aligned.m8n8.x4.shared.b16 {%0,%1,%2,%3}, [%4];"
        : "=r"(r0), "=r"(r1), "=r"(r2), "=r"(r3)
        : "r"(addr));
}
__device__ __forceinline__ void ldsm_x2(uint32_t& r0, uint32_t& r1,
                                        uint32_t addr) {
    asm volatile(
        "ldmatrix.sync.aligned.m8n8.x2.shared.b16 {%0,%1}, [%2];"
        : "=r"(r0), "=r"(r1)
        : "r"(addr));
}
__device__ __forceinline__ void mma_bf16(float* c, const uint32_t* a,
                                         const uint32_t* b) {
    asm volatile(
        "mma.sync.aligned.m16n8k16.row.col.f32.bf16.bf16.f32 "
        "{%0,%1,%2,%3}, {%4,%5,%6,%7}, {%8,%9}, {%0,%1,%2,%3};"
        : "+f"(c[0]), "+f"(c[1]), "+f"(c[2]), "+f"(c[3])
        : "r"(a[0]), "r"(a[1]), "r"(a[2]), "r"(a[3]), "r"(b[0]), "r"(b[1]));
}
__device__ __forceinline__ uint32_t pack_bf16(float a, float b) {
    __nv_bfloat162 p = __floats2bfloat162_rn(a, b);
    return *reinterpret_cast<uint32_t*>(&p);
}

__global__ __launch_bounds__(256) void transform_tc(
    const float* __restrict__ hin, const float* __restrict__ W) {
    extern __shared__ char smem[];
    char* Ahi_b = smem;
    char* Alo_b = smem + 32768;
    char* Whi_b = smem + 65536;
    char* Wlo_b = smem + 98304;

    const int t = threadIdx.x;
    const int lane = t & 31;
    const int warp = t >> 5;
    const int row0 = blockIdx.x * 128;

#pragma unroll
    for (int i = 0; i < 16; ++i) {
        const int idx = i * 256 + t;
        const int r = idx >> 5;
        const int c4 = idx & 31;
        const int gr = row0 + r;
        float4 a = (gr < N_NODES)
                       ? *reinterpret_cast<const float4*>(hin + (size_t)gr * D + c4 * 4)
                       : make_float4(0.f, 0.f, 0.f, 0.f);
        float h0 = __bfloat162float(__float2bfloat16(a.x));
        float h1 = __bfloat162float(__float2bfloat16(a.y));
        float h2 = __bfloat162float(__float2bfloat16(a.z));
        float h3 = __bfloat162float(__float2bfloat16(a.w));
        const int off = swz(r, c4 * 4);
        *reinterpret_cast<uint2*>(Ahi_b + off) =
            make_uint2(pack_bf16(a.x, a.y), pack_bf16(a.z, a.w));
        *reinterpret_cast<uint2*>(Alo_b + off) =
            make_uint2(pack_bf16(a.x - h0, a.y - h1), pack_bf16(a.z - h2, a.w - h3));
    }
#pragma unroll
    for (int i = 0; i < 16; ++i) {
        const int idx = i * 256 + t;
        const int r = idx >> 5;
        const int c4 = idx & 31;
        float4 a = *reinterpret_cast<const float4*>(W + r * D + c4 * 4);
        float h0 = __bfloat162float(__float2bfloat16(a.x));
        float h1 = __bfloat162float(__float2bfloat16(a.y));
        float h2 = __bfloat162float(__float2bfloat16(a.z));
        float h3 = __bfloat162float(__float2bfloat16(a.w));
        const int off = swz(r, c4 * 4);
        *reinterpret_cast<uint2*>(Whi_b + off) =
            make_uint2(pack_bf16(a.x, a.y), pack_bf16(a.z, a.w));
        *reinterpret_cast<uint2*>(Wlo_b + off) =
            make_uint2(pack_bf16(a.x - h0, a.y - h1), pack_bf16(a.z - h2, a.w - h3));
    }
    __syncthreads();

    const int wm0 = (warp & 3) * 32;
    const int wn0 = (warp >> 2) * 64;

    float c[2][8][4];
#pragma unroll
    for (int mt = 0; mt < 2; ++mt)
#pragma unroll
        for (int nt = 0; nt < 8; ++nt)
#pragma unroll
            for (int k = 0; k < 4; ++k) c[mt][nt][k] = 0.f;

    const uint32_t Ahi_s = smem_u32(Ahi_b);
    const uint32_t Alo_s = smem_u32(Alo_b);
    const uint32_t Whi_s = smem_u32(Whi_b);
    const uint32_t Wlo_s = smem_u32(Wlo_b);

    const int a_row_l = lane & 15;
    const int a_koff = (lane >> 4) * 8;
    const int b_row_l = lane & 7;
    const int b_koff = ((lane >> 3) & 1) * 8;

#pragma unroll
    for (int ks = 0; ks < 8; ++ks) {
        const int k0 = ks * 16;
        uint32_t ahi[2][4], alo[2][4];
#pragma unroll
        for (int mt = 0; mt < 2; ++mt) {
            const int off = swz(wm0 + mt * 16 + a_row_l, k0 + a_koff);
            ldsm_x4(ahi[mt][0], ahi[mt][1], ahi[mt][2], ahi[mt][3], Ahi_s + off);
            ldsm_x4(alo[mt][0], alo[mt][1], alo[mt][2], alo[mt][3], Alo_s + off);
        }
#pragma unroll
        for (int nt = 0; nt < 8; ++nt) {
            const int off = swz(wn0 + nt * 8 + b_row_l, k0 + b_koff);
            uint32_t bhi[2], blo[2];
            ldsm_x2(bhi[0], bhi[1], Whi_s + off);
            ldsm_x2(blo[0], blo[1], Wlo_s + off);
#pragma unroll
            for (int mt = 0; mt < 2; ++mt) {
                mma_bf16(c[mt][nt], ahi[mt], bhi);
                mma_bf16(c[mt][nt], ahi[mt], blo);
                mma_bf16(c[mt][nt], alo[mt], bhi);
            }
        }
    }

    const int qn = 2 * (lane & 3);
    const int qr = lane >> 2;
#pragma unroll
    for (int mt = 0; mt < 2; ++mt) {
        const int r_lo = row0 + wm0 + mt * 16 + qr;
        const int r_hi = r_lo + 8;
#pragma unroll
        for (int nt = 0; nt < 8; ++nt) {
            const int n = wn0 + nt * 8 + qn;
            if (r_lo < N_NODES)
                *reinterpret_cast<__half2*>(g_ht + (size_t)r_lo * D + n) =
                    __floats2half2_rn(c[mt][nt][0], c[mt][nt][1]);
            if (r_hi < N_NODES)
                *reinterpret_cast<__half2*>(g_ht + (size_t)r_hi * D + n) =
                    __floats2half2_rn(c[mt][nt][2], c[mt][nt][3]);
        }
    }
}

// ---------------------------------------------------------------------------
// Kernel 3: CSR SpMM, pair-gather + packed f32x2 FMA.
// Warp per row.  Lanes 0-15 process even edge of each pair, lanes 16-31 the
// odd edge (LDG.128 fetches two h' rows per warp load).  Metadata via
// lane-uniform int2/float2 broadcast loads + SEL (no shfl).  Accumulate with
// fma.rn.f32x2 (2 FMAs/instr).  p0 made even by a scalar head edge so all
// pair loads are aligned and the loop is mask-free.
// ---------------------------------------------------------------------------
__device__ __forceinline__ void fma8_x2(unsigned long long* acc, float v,
                                        const uint4& d) {
    unsigned long long v2;
    asm("mov.b64 %0, {%1, %1};" : "=l"(v2) : "f"(v));
    asm volatile(
        "{\n\t"
        ".reg .b16 h0, h1;\n\t"
        ".reg .f32 f0, f1;\n\t"
        ".reg .b64 fp;\n\t"
        "mov.b32 {h0, h1}, %4;\n\t"
        "cvt.f32.f16 f0, h0;\n\t"
        "cvt.f32.f16 f1, h1;\n\t"
        "mov.b64 fp, {f0, f1};\n\t"
        "fma.rn.f32x2 %0, fp, %8, %0;\n\t"
        "mov.b32 {h0, h1}, %5;\n\t"
        "cvt.f32.f16 f0, h0;\n\t"
        "cvt.f32.f16 f1, h1;\n\t"
        "mov.b64 fp, {f0, f1};\n\t"
        "fma.rn.f32x2 %1, fp, %8, %1;\n\t"
        "mov.b32 {h0, h1}, %6;\n\t"
        "cvt.f32.f16 f0, h0;\n\t"
        "cvt.f32.f16 f1, h1;\n\t"
        "mov.b64 fp, {f0, f1};\n\t"
        "fma.rn.f32x2 %2, fp, %8, %2;\n\t"
        "mov.b32 {h0, h1}, %7;\n\t"
        "cvt.f32.f16 f0, h0;\n\t"
        "cvt.f32.f16 f1, h1;\n\t"
        "mov.b64 fp, {f0, f1};\n\t"
        "fma.rn.f32x2 %3, fp, %8, %3;\n\t"
        "}"
        : "+l"(acc[0]), "+l"(acc[1]), "+l"(acc[2]), "+l"(acc[3])
        : "r"(d.x), "r"(d.y), "r"(d.z), "r"(d.w), "l"(v2));
}

__global__ __launch_bounds__(256) void spmm_pair2_kernel(
    const int* __restrict__ cols, const float* __restrict__ vals,
    const float* __restrict__ b, float* __restrict__ out) {
    const int warp = (blockIdx.x * blockDim.x + threadIdx.x) >> 5;
    const int lane = threadIdx.x & 31;
    if (warp >= N_NODES) return;
    const int row = warp;

    const int p0 = __ldg(&g_row_ptr[row]);
    const int p1 = __ldg(&g_row_ptr[row + 1]);

    const int half = lane >> 4;  // 0: even edge of pair, 1: odd
    const int fl = lane & 15;    // feature-lane (16B of the h' row)
    const char* htb = reinterpret_cast<const char*>(g_ht);
    const uint32_t foff = (uint32_t)fl << 4;

    unsigned long long acc[4] = {0ull, 0ull, 0ull, 0ull};  // 8 packed fp32

    int e = p0;
    // head: make e even (single uniform edge; half 1 contributes 0)
    if ((e & 1) && e < p1) {
        const int c = __ldg(cols + e);
        const float vv = __ldg(vals + e);
        const float v = (half == 0) ? vv : 0.f;
        const uint4 d =
            *reinterpret_cast<const uint4*>(htb + ((size_t)c << 8) + foff);
        fma8_x2(acc, v, d);
        ++e;
    }

    // steady loop: 4 pairs (8 edges) per iteration, mask-free
    for (; e + 8 <= p1; e += 8) {
        int2 cp[4];
        float2 vp[4];
        uint4 d[4];
#pragma unroll
        for (int i = 0; i < 4; ++i) {
            cp[i] = __ldg(reinterpret_cast<const int2*>(cols + e + 2 * i));
            vp[i] = __ldg(reinterpret_cast<const float2*>(vals + e + 2 * i));
        }
#pragma unroll
        for (int i = 0; i < 4; ++i) {
            const int c = half ? cp[i].y : cp[i].x;
            d[i] = *reinterpret_cast<const uint4*>(htb + ((size_t)c << 8) + foff);
        }
#pragma unroll
        for (int i = 0; i < 4; ++i) {
            const float v = half ? vp[i].y : vp[i].x;
            fma8_x2(acc, v, d[i]);
        }
    }
    // remaining full pairs
    for (; e + 2 <= p1; e += 2) {
        const int2 cp = __ldg(reinterpret_cast<const int2*>(cols + e));
        const float2 vp = __ldg(reinterpret_cast<const float2*>(vals + e));
        const int c = half ? cp.y : cp.x;
        const float v = half ? vp.y : vp.x;
        const uint4 d =
            *reinterpret_cast<const uint4*>(htb + ((size_t)c << 8) + foff);
        fma8_x2(acc, v, d);
    }
    // odd tail edge
    if (e < p1) {
        const int c = __ldg(cols + e);
        const float vv = __ldg(vals + e);
        const float v = (half == 0) ? vv : 0.f;
        const uint4 d =
            *reinterpret_cast<const uint4*>(htb + ((size_t)c << 8) + foff);
        fma8_x2(acc, v, d);
    }

    // unpack accumulators, merge half-warps, bias+relu+store
    float a[8];
#pragma unroll
    for (int q = 0; q < 4; ++q) {
        asm("mov.b64 {%0, %1}, %2;"
            : "=f"(a[2 * q]), "=f"(a[2 * q + 1])
            : "l"(acc[q]));
    }
#pragma unroll
    for (int i = 0; i < 8; ++i)
        a[i] += __shfl_xor_sync(0xffffffffu, a[i], 16);

    if (lane < 16) {
        const float4 b0 = __ldg(reinterpret_cast<const float4*>(b + fl * 8));
        const float4 b1 = __ldg(reinterpret_cast<const float4*>(b + fl * 8 + 4));
        float4 o0, o1;
        o0.x = fmaxf(a[0] + b0.x, 0.f);
        o0.y = fmaxf(a[1] + b0.y, 0.f);
        o0.z = fmaxf(a[2] + b0.z, 0.f);
        o0.w = fmaxf(a[3] + b0.w, 0.f);
        o1.x = fmaxf(a[4] + b1.x, 0.f);
        o1.y = fmaxf(a[5] + b1.y, 0.f);
        o1.z = fmaxf(a[6] + b1.z, 0.f);
        o1.w = fmaxf(a[7] + b1.w, 0.f);
        float* op = out + (size_t)row * D + fl * 8;
        *reinterpret_cast<float4*>(op) = o0;
        *reinterpret_cast<float4*>(op + 4) = o1;
    }
}

// ---------------------------------------------------------------------------
// Launch
// ---------------------------------------------------------------------------
extern "C" void kernel_launch(void* const* d_in, const int* in_sizes, int n_in,
                              void* d_out, int out_size) {
    const int* edge_rows = (const int*)d_in[0];
    const int* edge_cols = (const int*)d_in[1];
    const float* edge_vals = (const float*)d_in[2];
    const float* h = (const float*)d_in[3];
    const float* W = (const float*)d_in[4];
    const float* b = (const float*)d_in[5];
    float* out = (float*)d_out;

    const int E = in_sizes[0];

    static bool smem_set = false;
    if (!smem_set) {
        cudaFuncSetAttribute(transform_tc,
                             cudaFuncAttributeMaxDynamicSharedMemorySize,
                             GEMM_SMEM_BYTES);
        smem_set = true;
    }

    // 0) dummy — keeps ncu's captured launch on the SpMM kernel
    dummy_kernel<<<1, 32>>>();

    // 1) CSR row pointers
    rowptr_build<<<2048, 256>>>(edge_rows, E);

    // 2) h' = h @ W^T  (fp16)
    transform_tc<<<(N_NODES + 127) / 128, 256, GEMM_SMEM_BYTES>>>(h, W);

    // 3) pair-gather CSR SpMM -> relu(. + b) -> out
    const int sblocks = (N_NODES * 32 + 255) / 256;
    spmm_pair2_kernel<<<sblocks, 256>>>(edge_cols, edge_vals, b, out);
}

// round 9
// speedup vs baseline: 1.6829x; 1.1330x over previous
#include <cuda_runtime.h>
#include <cuda_fp16.h>
#include <cuda_bf16.h>
#include <cstdint>

#define N_NODES 100000
#define D 128
#define E_MAX 3200004

// Scratch (allocation-free rule: __device__ globals).
__device__ __half g_ht[(size_t)N_NODES * D];        // h @ W^T in fp16
__device__ int g_row_ptr[N_NODES + 2];              // CSR row pointers
__device__ __align__(16) uint2 g_meta[E_MAX];       // packed {col, val}

// ---------------------------------------------------------------------------
// Kernel 1: build row_ptr from sorted edge_rows.
// ---------------------------------------------------------------------------
__global__ __launch_bounds__(256) void rowptr_build(const int* __restrict__ rows,
                                                    int E) {
    const int tid = blockIdx.x * blockDim.x + threadIdx.x;
    const int ngroups = E >> 2;
    for (int g = tid; g < ngroups; g += gridDim.x * blockDim.x) {
        const int e = g * 4;
        const int4 r = *reinterpret_cast<const int4*>(rows + e);
        const int prev = (e == 0) ? -1 : __ldg(rows + e - 1);
        if (r.x != prev)
            for (int rr = prev + 1; rr <= r.x; ++rr) g_row_ptr[rr] = e;
        if (r.y != r.x)
            for (int rr = r.x + 1; rr <= r.y; ++rr) g_row_ptr[rr] = e + 1;
        if (r.z != r.y)
            for (int rr = r.y + 1; rr <= r.z; ++rr) g_row_ptr[rr] = e + 2;
        if (r.w != r.z)
            for (int rr = r.z + 1; rr <= r.w; ++rr) g_row_ptr[rr] = e + 3;
    }
    if (tid == 0) {
        for (int e = ngroups * 4; e < E; ++e) {
            const int pr = (e == 0) ? -1 : __ldg(rows + e - 1);
            const int r = __ldg(rows + e);
            for (int rr = pr + 1; rr <= r; ++rr) g_row_ptr[rr] = e;
        }
        const int last = (E > 0) ? __ldg(rows + E - 1) : -1;
        for (int rr = last + 1; rr <= N_NODES; ++rr) g_row_ptr[rr] = E;
    }
}

// ---------------------------------------------------------------------------
// Kernel 2: pack edge metadata: g_meta[e] = {col[e], bits(val[e])}.
// ---------------------------------------------------------------------------
__global__ __launch_bounds__(256) void prep_meta(const int* __restrict__ cols,
                                                 const float* __restrict__ vals,
                                                 int E) {
    const int tid = blockIdx.x * blockDim.x + threadIdx.x;
    const int ngroups = E >> 2;
    uint4* mp = reinterpret_cast<uint4*>(g_meta);
    for (int g = tid; g < ngroups; g += gridDim.x * blockDim.x) {
        const int e = g * 4;
        const int4 c = *reinterpret_cast<const int4*>(cols + e);
        const float4 v = *reinterpret_cast<const float4*>(vals + e);
        mp[g * 2 + 0] = make_uint4((uint32_t)c.x, __float_as_uint(v.x),
                                   (uint32_t)c.y, __float_as_uint(v.y));
        mp[g * 2 + 1] = make_uint4((uint32_t)c.z, __float_as_uint(v.z),
                                   (uint32_t)c.w, __float_as_uint(v.w));
    }
    if (tid == 0) {
        for (int e = ngroups * 4; e < E; ++e)
            g_meta[e] = make_uint2((uint32_t)__ldg(cols + e),
                                   __float_as_uint(__ldg(vals + e)));
    }
}

// ---------------------------------------------------------------------------
// Kernel 3: h' = h @ W^T, single-pass fp16 tensor cores, fp16 output.
// smem = A(32KB) + W(32KB) = 64KB -> 3 blocks/SM (vs 1 for the split version).
// ---------------------------------------------------------------------------
#define GEMM_SMEM_BYTES (2 * 128 * 256)  // Ah, Wh : 32KB each

__device__ __forceinline__ int swz(int row, int col /*fp16 units*/) {
    return row * 256 + (((col * 2) ^ ((row & 7) << 4)));
}
__device__ __forceinline__ uint32_t smem_u32(const void* p) {
    return (uint32_t)__cvta_generic_to_shared(p);
}
__device__ __forceinline__ void ldsm_x4(uint32_t& r0, uint32_t& r1,
                                        uint32_t& r2, uint32_t& r3,
                                        uint32_t addr) {
    asm volatile(
        "ldmatrix.sync.aligned.m8n8.x4.shared.b16 {%0,%1,%2,%3}, [%4];"
        : "=r"(r0), "=r"(r1), "=r"(r2), "=r"(r3)
        : "r"(addr));
}
__device__ __forceinline__ void ldsm_x2(uint32_t& r0, uint32_t& r1,
                                        uint32_t addr) {
    asm volatile(
        "ldmatrix.sync.aligned.m8n8.x2.shared.b16 {%0,%1}, [%2];"
        : "=r"(r0), "=r"(r1)
        : "r"(addr));
}
__device__ __forceinline__ void mma_f16(float* c, const uint32_t* a,
                                        const uint32_t* b) {
    asm volatile(
        "mma.sync.aligned.m16n8k16.row.col.f32.f16.f16.f32 "
        "{%0,%1,%2,%3}, {%4,%5,%6,%7}, {%8,%9}, {%0,%1,%2,%3};"
        : "+f"(c[0]), "+f"(c[1]), "+f"(c[2]), "+f"(c[3])
        : "r"(a[0]), "r"(a[1]), "r"(a[2]), "r"(a[3]), "r"(b[0]), "r"(b[1]));
}
__device__ __forceinline__ uint32_t pack_f16(float a, float b) {
    __half2 p = __floats2half2_rn(a, b);
    return *reinterpret_cast<uint32_t*>(&p);
}

__global__ __launch_bounds__(256) void transform_f16(
    const float* __restrict__ hin, const float* __restrict__ W) {
    extern __shared__ char smem[];
    char* Ah_b = smem;
    char* Wh_b = smem + 32768;

    const int t = threadIdx.x;
    const int lane = t & 31;
    const int warp = t >> 5;
    const int row0 = blockIdx.x * 128;

    // load + fp16-convert A (h) tile: 128x128 fp32, 16 float4/thread
#pragma unroll
    for (int i = 0; i < 16; ++i) {
        const int idx = i * 256 + t;
        const int r = idx >> 5;
        const int c4 = idx & 31;
        const int gr = row0 + r;
        float4 a = (gr < N_NODES)
                       ? *reinterpret_cast<const float4*>(hin + (size_t)gr * D + c4 * 4)
                       : make_float4(0.f, 0.f, 0.f, 0.f);
        *reinterpret_cast<uint2*>(Ah_b + swz(r, c4 * 4)) =
            make_uint2(pack_f16(a.x, a.y), pack_f16(a.z, a.w));
    }
    // load + fp16-convert W tile
#pragma unroll
    for (int i = 0; i < 16; ++i) {
        const int idx = i * 256 + t;
        const int r = idx >> 5;
        const int c4 = idx & 31;
        const float4 a = *reinterpret_cast<const float4*>(W + r * D + c4 * 4);
        *reinterpret_cast<uint2*>(Wh_b + swz(r, c4 * 4)) =
            make_uint2(pack_f16(a.x, a.y), pack_f16(a.z, a.w));
    }
    __syncthreads();

    // warp tile: 32 m x 64 n;  warps: 4(m) x 2(n)
    const int wm0 = (warp & 3) * 32;
    const int wn0 = (warp >> 2) * 64;

    float c[2][8][4];
#pragma unroll
    for (int mt = 0; mt < 2; ++mt)
#pragma unroll
        for (int nt = 0; nt < 8; ++nt)
#pragma unroll
            for (int k = 0; k < 4; ++k) c[mt][nt][k] = 0.f;

    const uint32_t Ah_s = smem_u32(Ah_b);
    const uint32_t Wh_s = smem_u32(Wh_b);

    const int a_row_l = lane & 15;
    const int a_koff = (lane >> 4) * 8;
    const int b_row_l = lane & 7;
    const int b_koff = ((lane >> 3) & 1) * 8;

#pragma unroll
    for (int ks = 0; ks < 8; ++ks) {
        const int k0 = ks * 16;
        uint32_t af[2][4];
#pragma unroll
        for (int mt = 0; mt < 2; ++mt) {
            const int off = swz(wm0 + mt * 16 + a_row_l, k0 + a_koff);
            ldsm_x4(af[mt][0], af[mt][1], af[mt][2], af[mt][3], Ah_s + off);
        }
#pragma unroll
        for (int nt = 0; nt < 8; ++nt) {
            const int off = swz(wn0 + nt * 8 + b_row_l, k0 + b_koff);
            uint32_t bf[2];
            ldsm_x2(bf[0], bf[1], Wh_s + off);
#pragma unroll
            for (int mt = 0; mt < 2; ++mt) mma_f16(c[mt][nt], af[mt], bf);
        }
    }

    // epilogue: fp16 store
    const int qn = 2 * (lane & 3);
    const int qr = lane >> 2;
#pragma unroll
    for (int mt = 0; mt < 2; ++mt) {
        const int r_lo = row0 + wm0 + mt * 16 + qr;
        const int r_hi = r_lo + 8;
#pragma unroll
        for (int nt = 0; nt < 8; ++nt) {
            const int n = wn0 + nt * 8 + qn;
            if (r_lo < N_NODES)
                *reinterpret_cast<__half2*>(g_ht + (size_t)r_lo * D + n) =
                    __floats2half2_rn(c[mt][nt][0], c[mt][nt][1]);
            if (r_hi < N_NODES)
                *reinterpret_cast<__half2*>(g_ht + (size_t)r_hi * D + n) =
                    __floats2half2_rn(c[mt][nt][2], c[mt][nt][3]);
        }
    }
}

// ---------------------------------------------------------------------------
// Kernel 4: CSR SpMM, pair-gather + packed f32x2 FMA + packed metadata.
// Warp per row.  Lanes 0-15 process the even edge of each pair, lanes 16-31
// the odd edge (one LDG.128 fetches 16B of a h' row per lane -> two rows per
// warp load).  Metadata: ONE uniform LDG.128 per pair from g_meta + 2 SEL.
// ---------------------------------------------------------------------------
__device__ __forceinline__ void fma8_x2(unsigned long long* acc, float v,
                                        const uint4& d) {
    unsigned long long v2;
    asm("mov.b64 %0, {%1, %1};" : "=l"(v2) : "f"(v));
    asm volatile(
        "{\n\t"
        ".reg .b16 h0, h1;\n\t"
        ".reg .f32 f0, f1;\n\t"
        ".reg .b64 fp;\n\t"
        "mov.b32 {h0, h1}, %4;\n\t"
        "cvt.f32.f16 f0, h0;\n\t"
        "cvt.f32.f16 f1, h1;\n\t"
        "mov.b64 fp, {f0, f1};\n\t"
        "fma.rn.f32x2 %0, fp, %8, %0;\n\t"
        "mov.b32 {h0, h1}, %5;\n\t"
        "cvt.f32.f16 f0, h0;\n\t"
        "cvt.f32.f16 f1, h1;\n\t"
        "mov.b64 fp, {f0, f1};\n\t"
        "fma.rn.f32x2 %1, fp, %8, %1;\n\t"
        "mov.b32 {h0, h1}, %6;\n\t"
        "cvt.f32.f16 f0, h0;\n\t"
        "cvt.f32.f16 f1, h1;\n\t"
        "mov.b64 fp, {f0, f1};\n\t"
        "fma.rn.f32x2 %2, fp, %8, %2;\n\t"
        "mov.b32 {h0, h1}, %7;\n\t"
        "cvt.f32.f16 f0, h0;\n\t"
        "cvt.f32.f16 f1, h1;\n\t"
        "mov.b64 fp, {f0, f1};\n\t"
        "fma.rn.f32x2 %3, fp, %8, %3;\n\t"
        "}"
        : "+l"(acc[0]), "+l"(acc[1]), "+l"(acc[2]), "+l"(acc[3])
        : "r"(d.x), "r"(d.y), "r"(d.z), "r"(d.w), "l"(v2));
}

__global__ __launch_bounds__(256) void spmm_pair3_kernel(
    const float* __restrict__ b, float* __restrict__ out) {
    const int warp = (blockIdx.x * blockDim.x + threadIdx.x) >> 5;
    const int lane = threadIdx.x & 31;
    if (warp >= N_NODES) return;
    const int row = warp;

    const int p0 = __ldg(&g_row_ptr[row]);
    const int p1 = __ldg(&g_row_ptr[row + 1]);

    const int half = lane >> 4;  // 0: even edge of pair, 1: odd
    const int fl = lane & 15;    // feature-lane (16B of the h' row)
    const char* htb = reinterpret_cast<const char*>(g_ht);
    const uint32_t foff = (uint32_t)fl << 4;

    unsigned long long acc[4] = {0ull, 0ull, 0ull, 0ull};  // 8 packed fp32

    int e = p0;
    // head: make e even (single uniform edge; half 1 contributes 0)
    if ((e & 1) && e < p1) {
        const uint2 m = __ldg(&g_meta[e]);
        const float v = (half == 0) ? __uint_as_float(m.y) : 0.f;
        const uint4 d = *reinterpret_cast<const uint4*>(
            htb + ((size_t)m.x << 8) + foff);
        fma8_x2(acc, v, d);
        ++e;
    }

    // steady loop: 4 pairs (8 edges) per iteration, mask-free
    for (; e + 8 <= p1; e += 8) {
        uint4 m[4];
        uint4 d[4];
#pragma unroll
        for (int i = 0; i < 4; ++i)
            m[i] = __ldg(reinterpret_cast<const uint4*>(g_meta + e + 2 * i));
#pragma unroll
        for (int i = 0; i < 4; ++i) {
            const uint32_t c = half ? m[i].z : m[i].x;
            d[i] = *reinterpret_cast<const uint4*>(htb + ((size_t)c << 8) + foff);
        }
#pragma unroll
        for (int i = 0; i < 4; ++i) {
            const float v = __uint_as_float(half ? m[i].w : m[i].y);
            fma8_x2(acc, v, d[i]);
        }
    }
    // remaining full pairs
    for (; e + 2 <= p1; e += 2) {
        const uint4 m = __ldg(reinterpret_cast<const uint4*>(g_meta + e));
        const uint32_t c = half ? m.z : m.x;
        const float v = __uint_as_float(half ? m.w : m.y);
        const uint4 d =
            *reinterpret_cast<const uint4*>(htb + ((size_t)c << 8) + foff);
        fma8_x2(acc, v, d);
    }
    // odd tail edge
    if (e < p1) {
        const uint2 m = __ldg(&g_meta[e]);
        const float v = (half == 0) ? __uint_as_float(m.y) : 0.f;
        const uint4 d = *reinterpret_cast<const uint4*>(
            htb + ((size_t)m.x << 8) + foff);
        fma8_x2(acc, v, d);
    }

    // unpack accumulators, merge half-warps, bias+relu+store
    float a[8];
#pragma unroll
    for (int q = 0; q < 4; ++q) {
        asm("mov.b64 {%0, %1}, %2;"
            : "=f"(a[2 * q]), "=f"(a[2 * q + 1])
            : "l"(acc[q]));
    }
#pragma unroll
    for (int i = 0; i < 8; ++i)
        a[i] += __shfl_xor_sync(0xffffffffu, a[i], 16);

    if (lane < 16) {
        const float4 b0 = __ldg(reinterpret_cast<const float4*>(b + fl * 8));
        const float4 b1 = __ldg(reinterpret_cast<const float4*>(b + fl * 8 + 4));
        float4 o0, o1;
        o0.x = fmaxf(a[0] + b0.x, 0.f);
        o0.y = fmaxf(a[1] + b0.y, 0.f);
        o0.z = fmaxf(a[2] + b0.z, 0.f);
        o0.w = fmaxf(a[3] + b0.w, 0.f);
        o1.x = fmaxf(a[4] + b1.x, 0.f);
        o1.y = fmaxf(a[5] + b1.y, 0.f);
        o1.z = fmaxf(a[6] + b1.z, 0.f);
        o1.w = fmaxf(a[7] + b1.w, 0.f);
        float* op = out + (size_t)row * D + fl * 8;
        *reinterpret_cast<float4*>(op) = o0;
        *reinterpret_cast<float4*>(op + 4) = o1;
    }
}

// ---------------------------------------------------------------------------
// Launch
// ---------------------------------------------------------------------------
extern "C" void kernel_launch(void* const* d_in, const int* in_sizes, int n_in,
                              void* d_out, int out_size) {
    const int* edge_rows = (const int*)d_in[0];
    const int* edge_cols = (const int*)d_in[1];
    const float* edge_vals = (const float*)d_in[2];
    const float* h = (const float*)d_in[3];
    const float* W = (const float*)d_in[4];
    const float* b = (const float*)d_in[5];
    float* out = (float*)d_out;

    const int E = in_sizes[0];

    static bool smem_set = false;
    if (!smem_set) {
        cudaFuncSetAttribute(transform_f16,
                             cudaFuncAttributeMaxDynamicSharedMemorySize,
                             GEMM_SMEM_BYTES);
        smem_set = true;
    }

    // 1) CSR row pointers
    rowptr_build<<<2048, 256>>>(edge_rows, E);

    // 2) packed edge metadata
    prep_meta<<<2048, 256>>>(edge_cols, edge_vals, E);

    // 3) h' = h @ W^T  (single-pass fp16 tensor cores)
    transform_f16<<<(N_NODES + 127) / 128, 256, GEMM_SMEM_BYTES>>>(h, W);

    // 4) pair-gather CSR SpMM -> relu(. + b) -> out
    const int sblocks = (N_NODES * 32 + 255) / 256;
    spmm_pair3_kernel<<<sblocks, 256>>>(b, out);
}

// round 10
// speedup vs baseline: 1.8353x; 1.0906x over previous
#include <cuda_runtime.h>
#include <cuda_fp16.h>
#include <cuda_bf16.h>
#include <cstdint>

#define N_NODES 100000
#define D 128
#define E_MAX 3200004

// Scratch (allocation-free rule: __device__ globals).
__device__ __half g_ht[(size_t)N_NODES * D];    // h @ W^T in fp16
__device__ int g_row_ptr[N_NODES + 2];          // CSR row pointers
__device__ __align__(16) uint2 g_meta[E_MAX];   // {col<<8, half2(v,v)}

// ---------------------------------------------------------------------------
// Kernel 1: fused prep — build row_ptr AND packed meta in one pass.
// meta[e] = { col[e]*256 (byte offset of h' row),  half2(val, val) }.
// ---------------------------------------------------------------------------
__device__ __forceinline__ uint32_t dup_h2(float v) {
    const __half2 h = __half2half2(__float2half_rn(v));
    return *reinterpret_cast<const uint32_t*>(&h);
}

__global__ __launch_bounds__(256) void prep_fused(const int* __restrict__ rows,
                                                  const int* __restrict__ cols,
                                                  const float* __restrict__ vals,
                                                  int E) {
    const int tid = blockIdx.x * blockDim.x + threadIdx.x;
    const int ngroups = E >> 2;
    uint4* mp = reinterpret_cast<uint4*>(g_meta);
    for (int g = tid; g < ngroups; g += gridDim.x * blockDim.x) {
        const int e = g * 4;
        // ---- rowptr transitions
        const int4 r = *reinterpret_cast<const int4*>(rows + e);
        const int prev = (e == 0) ? -1 : __ldg(rows + e - 1);
        if (r.x != prev)
            for (int rr = prev + 1; rr <= r.x; ++rr) g_row_ptr[rr] = e;
        if (r.y != r.x)
            for (int rr = r.x + 1; rr <= r.y; ++rr) g_row_ptr[rr] = e + 1;
        if (r.z != r.y)
            for (int rr = r.y + 1; rr <= r.z; ++rr) g_row_ptr[rr] = e + 2;
        if (r.w != r.z)
            for (int rr = r.z + 1; rr <= r.w; ++rr) g_row_ptr[rr] = e + 3;
        // ---- packed meta
        const int4 c = *reinterpret_cast<const int4*>(cols + e);
        const float4 v = *reinterpret_cast<const float4*>(vals + e);
        mp[g * 2 + 0] = make_uint4((uint32_t)c.x << 8, dup_h2(v.x),
                                   (uint32_t)c.y << 8, dup_h2(v.y));
        mp[g * 2 + 1] = make_uint4((uint32_t)c.z << 8, dup_h2(v.z),
                                   (uint32_t)c.w << 8, dup_h2(v.w));
    }
    if (tid == 0) {
        for (int e = ngroups * 4; e < E; ++e) {
            const int pr = (e == 0) ? -1 : __ldg(rows + e - 1);
            const int r = __ldg(rows + e);
            for (int rr = pr + 1; rr <= r; ++rr) g_row_ptr[rr] = e;
            g_meta[e] = make_uint2((uint32_t)__ldg(cols + e) << 8,
                                   dup_h2(__ldg(vals + e)));
        }
        const int last = (E > 0) ? __ldg(rows + E - 1) : -1;
        for (int rr = last + 1; rr <= N_NODES; ++rr) g_row_ptr[rr] = E;
    }
}

// ---------------------------------------------------------------------------
// Kernel 2: h' = h @ W^T, single-pass fp16 tensor cores, fp16 output.
// ---------------------------------------------------------------------------
#define GEMM_SMEM_BYTES (2 * 128 * 256)  // Ah, Wh : 32KB each

__device__ __forceinline__ int swz(int row, int col /*fp16 units*/) {
    return row * 256 + (((col * 2) ^ ((row & 7) << 4)));
}
__device__ __forceinline__ uint32_t smem_u32(const void* p) {
    return (uint32_t)__cvta_generic_to_shared(p);
}
__device__ __forceinline__ void ldsm_x4(uint32_t& r0, uint32_t& r1,
                                        uint32_t& r2, uint32_t& r3,
                                        uint32_t addr) {
    asm volatile(
        "ldmatrix.sync.aligned.m8n8.x4.shared.b16 {%0,%1,%2,%3}, [%4];"
        : "=r"(r0), "=r"(r1), "=r"(r2), "=r"(r3)
        : "r"(addr));
}
__device__ __forceinline__ void ldsm_x2(uint32_t& r0, uint32_t& r1,
                                        uint32_t addr) {
    asm volatile(
        "ldmatrix.sync.aligned.m8n8.x2.shared.b16 {%0,%1}, [%2];"
        : "=r"(r0), "=r"(r1)
        : "r"(addr));
}
__device__ __forceinline__ void mma_f16(float* c, const uint32_t* a,
                                        const uint32_t* b) {
    asm volatile(
        "mma.sync.aligned.m16n8k16.row.col.f32.f16.f16.f32 "
        "{%0,%1,%2,%3}, {%4,%5,%6,%7}, {%8,%9}, {%0,%1,%2,%3};"
        : "+f"(c[0]), "+f"(c[1]), "+f"(c[2]), "+f"(c[3])
        : "r"(a[0]), "r"(a[1]), "r"(a[2]), "r"(a[3]), "r"(b[0]), "r"(b[1]));
}
__device__ __forceinline__ uint32_t pack_f16(float a, float b) {
    __half2 p = __floats2half2_rn(a, b);
    return *reinterpret_cast<uint32_t*>(&p);
}

__global__ __launch_bounds__(256) void transform_f16(
    const float* __restrict__ hin, const float* __restrict__ W) {
    extern __shared__ char smem[];
    char* Ah_b = smem;
    char* Wh_b = smem + 32768;

    const int t = threadIdx.x;
    const int lane = t & 31;
    const int warp = t >> 5;
    const int row0 = blockIdx.x * 128;

#pragma unroll
    for (int i = 0; i < 16; ++i) {
        const int idx = i * 256 + t;
        const int r = idx >> 5;
        const int c4 = idx & 31;
        const int gr = row0 + r;
        float4 a = (gr < N_NODES)
                       ? *reinterpret_cast<const float4*>(hin + (size_t)gr * D + c4 * 4)
                       : make_float4(0.f, 0.f, 0.f, 0.f);
        *reinterpret_cast<uint2*>(Ah_b + swz(r, c4 * 4)) =
            make_uint2(pack_f16(a.x, a.y), pack_f16(a.z, a.w));
    }
#pragma unroll
    for (int i = 0; i < 16; ++i) {
        const int idx = i * 256 + t;
        const int r = idx >> 5;
        const int c4 = idx & 31;
        const float4 a = *reinterpret_cast<const float4*>(W + r * D + c4 * 4);
        *reinterpret_cast<uint2*>(Wh_b + swz(r, c4 * 4)) =
            make_uint2(pack_f16(a.x, a.y), pack_f16(a.z, a.w));
    }
    __syncthreads();

    const int wm0 = (warp & 3) * 32;
    const int wn0 = (warp >> 2) * 64;

    float c[2][8][4];
#pragma unroll
    for (int mt = 0; mt < 2; ++mt)
#pragma unroll
        for (int nt = 0; nt < 8; ++nt)
#pragma unroll
            for (int k = 0; k < 4; ++k) c[mt][nt][k] = 0.f;

    const uint32_t Ah_s = smem_u32(Ah_b);
    const uint32_t Wh_s = smem_u32(Wh_b);

    const int a_row_l = lane & 15;
    const int a_koff = (lane >> 4) * 8;
    const int b_row_l = lane & 7;
    const int b_koff = ((lane >> 3) & 1) * 8;

#pragma unroll
    for (int ks = 0; ks < 8; ++ks) {
        const int k0 = ks * 16;
        uint32_t af[2][4];
#pragma unroll
        for (int mt = 0; mt < 2; ++mt) {
            const int off = swz(wm0 + mt * 16 + a_row_l, k0 + a_koff);
            ldsm_x4(af[mt][0], af[mt][1], af[mt][2], af[mt][3], Ah_s + off);
        }
#pragma unroll
        for (int nt = 0; nt < 8; ++nt) {
            const int off = swz(wn0 + nt * 8 + b_row_l, k0 + b_koff);
            uint32_t bf[2];
            ldsm_x2(bf[0], bf[1], Wh_s + off);
#pragma unroll
            for (int mt = 0; mt < 2; ++mt) mma_f16(c[mt][nt], af[mt], bf);
        }
    }

    const int qn = 2 * (lane & 3);
    const int qr = lane >> 2;
#pragma unroll
    for (int mt = 0; mt < 2; ++mt) {
        const int r_lo = row0 + wm0 + mt * 16 + qr;
        const int r_hi = r_lo + 8;
#pragma unroll
        for (int nt = 0; nt < 8; ++nt) {
            const int n = wn0 + nt * 8 + qn;
            if (r_lo < N_NODES)
                *reinterpret_cast<__half2*>(g_ht + (size_t)r_lo * D + n) =
                    __floats2half2_rn(c[mt][nt][0], c[mt][nt][1]);
            if (r_hi < N_NODES)
                *reinterpret_cast<__half2*>(g_ht + (size_t)r_hi * D + n) =
                    __floats2half2_rn(c[mt][nt][2], c[mt][nt][3]);
        }
    }
}

// ---------------------------------------------------------------------------
// Kernel 3: CSR SpMM, pair-gather + fp16 window accumulation.
// Warp per row; lanes 0-15 handle the even edge of each pair, lanes 16-31 the
// odd edge.  Meta: ONE lane-divergent LDG.64 per edge-half (no SEL, no dup).
// Inner: 4 HFMA2 per edge into a 4-edge fp16 window, flushed to fp32 once
// per 8-edge iteration (2 inst/edge).  ~6-7 warp-inst/edge total.
// ---------------------------------------------------------------------------
__global__ __launch_bounds__(256) void spmm_h2_kernel(
    const float* __restrict__ b, float* __restrict__ out) {
    const int warp = (blockIdx.x * blockDim.x + threadIdx.x) >> 5;
    const int lane = threadIdx.x & 31;
    if (warp >= N_NODES) return;
    const int row = warp;

    const int p0 = __ldg(&g_row_ptr[row]);
    const int p1 = __ldg(&g_row_ptr[row + 1]);

    const int half = lane >> 4;  // 0: even edge of pair, 1: odd
    const int fl = lane & 15;    // feature-lane (16B of the h' row)
    const char* htb = reinterpret_cast<const char*>(g_ht);
    const uint32_t foff = (uint32_t)fl << 4;

    float a[8];
#pragma unroll
    for (int i = 0; i < 8; ++i) a[i] = 0.f;

    // fp32 path for masked head/tail edges (rare)
    auto edge_f32 = [&](int e, bool use) {
        const uint2 m = __ldg(&g_meta[e]);
        const uint4 d =
            *reinterpret_cast<const uint4*>(htb + m.x + foff);
        const __half2 vh = *reinterpret_cast<const __half2*>(&m.y);
        const float v = use ? __half2float(__low2half(vh)) : 0.f;
        const __half2* hp = reinterpret_cast<const __half2*>(&d);
#pragma unroll
        for (int q = 0; q < 4; ++q) {
            const float2 f = __half22float2(hp[q]);
            a[2 * q + 0] = fmaf(v, f.x, a[2 * q + 0]);
            a[2 * q + 1] = fmaf(v, f.y, a[2 * q + 1]);
        }
    };

    int e = p0;
    if ((e & 1) && e < p1) {  // head: make e even
        edge_f32(e, half == 0);
        ++e;
    }

    const __half2 hz = __float2half2_rn(0.f);

    // steady loop: 8 edges (4 pairs); each half-warp windows its 4 edges in
    // fp16 and flushes to fp32 once.
    for (; e + 8 <= p1; e += 8) {
        const uint2 m0 = __ldg(g_meta + e + 0 + half);
        const uint2 m1 = __ldg(g_meta + e + 2 + half);
        const uint2 m2 = __ldg(g_meta + e + 4 + half);
        const uint2 m3 = __ldg(g_meta + e + 6 + half);

        const uint4 d0 = *reinterpret_cast<const uint4*>(htb + m0.x + foff);
        const uint4 d1 = *reinterpret_cast<const uint4*>(htb + m1.x + foff);
        const uint4 d2 = *reinterpret_cast<const uint4*>(htb + m2.x + foff);
        const uint4 d3 = *reinterpret_cast<const uint4*>(htb + m3.x + foff);

        __half2 w0 = hz, w1 = hz, w2 = hz, w3 = hz;
        {
            const __half2 v = *reinterpret_cast<const __half2*>(&m0.y);
            const __half2* hp = reinterpret_cast<const __half2*>(&d0);
            w0 = __hfma2(hp[0], v, w0);
            w1 = __hfma2(hp[1], v, w1);
            w2 = __hfma2(hp[2], v, w2);
            w3 = __hfma2(hp[3], v, w3);
        }
        {
            const __half2 v = *reinterpret_cast<const __half2*>(&m1.y);
            const __half2* hp = reinterpret_cast<const __half2*>(&d1);
            w0 = __hfma2(hp[0], v, w0);
            w1 = __hfma2(hp[1], v, w1);
            w2 = __hfma2(hp[2], v, w2);
            w3 = __hfma2(hp[3], v, w3);
        }
        {
            const __half2 v = *reinterpret_cast<const __half2*>(&m2.y);
            const __half2* hp = reinterpret_cast<const __half2*>(&d2);
            w0 = __hfma2(hp[0], v, w0);
            w1 = __hfma2(hp[1], v, w1);
            w2 = __hfma2(hp[2], v, w2);
            w3 = __hfma2(hp[3], v, w3);
        }
        {
            const __half2 v = *reinterpret_cast<const __half2*>(&m3.y);
            const __half2* hp = reinterpret_cast<const __half2*>(&d3);
            w0 = __hfma2(hp[0], v, w0);
            w1 = __hfma2(hp[1], v, w1);
            w2 = __hfma2(hp[2], v, w2);
            w3 = __hfma2(hp[3], v, w3);
        }
        // flush window to fp32
        {
            const float2 f0 = __half22float2(w0);
            const float2 f1 = __half22float2(w1);
            const float2 f2 = __half22float2(w2);
            const float2 f3 = __half22float2(w3);
            a[0] += f0.x; a[1] += f0.y;
            a[2] += f1.x; a[3] += f1.y;
            a[4] += f2.x; a[5] += f2.y;
            a[6] += f3.x; a[7] += f3.y;
        }
    }
    // remaining full pairs (fp32 path, no mask needed)
    for (; e + 2 <= p1; e += 2) {
        const uint2 m = __ldg(g_meta + e + half);
        const uint4 d = *reinterpret_cast<const uint4*>(htb + m.x + foff);
        const __half2 vh = *reinterpret_cast<const __half2*>(&m.y);
        const float v = __half2float(__low2half(vh));
        const __half2* hp = reinterpret_cast<const __half2*>(&d);
#pragma unroll
        for (int q = 0; q < 4; ++q) {
            const float2 f = __half22float2(hp[q]);
            a[2 * q + 0] = fmaf(v, f.x, a[2 * q + 0]);
            a[2 * q + 1] = fmaf(v, f.y, a[2 * q + 1]);
        }
    }
    // odd tail edge
    if (e < p1) edge_f32(e, half == 0);

    // merge the two half-warp accumulators, bias + relu + store
#pragma unroll
    for (int i = 0; i < 8; ++i)
        a[i] += __shfl_xor_sync(0xffffffffu, a[i], 16);

    if (lane < 16) {
        const float4 b0 = __ldg(reinterpret_cast<const float4*>(b + fl * 8));
        const float4 b1 = __ldg(reinterpret_cast<const float4*>(b + fl * 8 + 4));
        float4 o0, o1;
        o0.x = fmaxf(a[0] + b0.x, 0.f);
        o0.y = fmaxf(a[1] + b0.y, 0.f);
        o0.z = fmaxf(a[2] + b0.z, 0.f);
        o0.w = fmaxf(a[3] + b0.w, 0.f);
        o1.x = fmaxf(a[4] + b1.x, 0.f);
        o1.y = fmaxf(a[5] + b1.y, 0.f);
        o1.z = fmaxf(a[6] + b1.z, 0.f);
        o1.w = fmaxf(a[7] + b1.w, 0.f);
        float* op = out + (size_t)row * D + fl * 8;
        *reinterpret_cast<float4*>(op) = o0;
        *reinterpret_cast<float4*>(op + 4) = o1;
    }
}

// ---------------------------------------------------------------------------
// Launch
// ---------------------------------------------------------------------------
extern "C" void kernel_launch(void* const* d_in, const int* in_sizes, int n_in,
                              void* d_out, int out_size) {
    const int* edge_rows = (const int*)d_in[0];
    const int* edge_cols = (const int*)d_in[1];
    const float* edge_vals = (const float*)d_in[2];
    const float* h = (const float*)d_in[3];
    const float* W = (const float*)d_in[4];
    const float* b = (const float*)d_in[5];
    float* out = (float*)d_out;

    const int E = in_sizes[0];

    static bool smem_set = false;
    if (!smem_set) {
        cudaFuncSetAttribute(transform_f16,
                             cudaFuncAttributeMaxDynamicSharedMemorySize,
                             GEMM_SMEM_BYTES);
        smem_set = true;
    }

    // 1) fused rowptr + packed meta
    prep_fused<<<2048, 256>>>(edge_rows, edge_cols, edge_vals, E);

    // 2) h' = h @ W^T  (single-pass fp16 tensor cores)
    transform_f16<<<(N_NODES + 127) / 128, 256, GEMM_SMEM_BYTES>>>(h, W);

    // 3) pair-gather CSR SpMM (fp16 window accumulation) -> relu(. + b) -> out
    const int sblocks = (N_NODES * 32 + 255) / 256;
    spmm_h2_kernel<<<sblocks, 256>>>(b, out);
}